// round 11
// baseline (speedup 1.0000x reference)
#include <cuda_runtime.h>
#include <math.h>
#include <stdint.h>

// ================= static scratch (no allocations allowed) =================
__device__ uint32_t g_xs_h [4096u*1024], g_xs_l [4096u*1024];   // x split [4096][1024p]
__device__ uint32_t g_wd_h [2112u*1024], g_wd_l [2112u*1024];   // wq_down(1536)|wkv_down(512)|wk_rope(64)
__device__ uint32_t g_wqc_h[3072u*768],  g_wqc_l[3072u*768];    // wq_up(2048) | wq_rope(1024)
__device__ uint32_t g_wkvu_h[4096u*256], g_wkvu_l[4096u*256];   // wkv_up
__device__ uint32_t g_wo_h [2048u*1024], g_wo_l [2048u*1024];   // wo
__device__ float    g_dcat [4096u*2112];                        // q_c(1536) | kv_c(512) | krope(64)
__device__ uint32_t g_qcs_h[4096u*768],  g_qcs_l[4096u*768];    // normed q_c split
__device__ uint32_t g_kvcs_h[4096u*256], g_kvcs_l[4096u*256];   // normed kv_c split
__device__ float    g_qup  [4096ull*3072];                      // qnope(2048) | qpe(1024)
__device__ float    g_kvup [4096ull*4096];                      // per head: k_nope(128)|v(128)
__device__ uint32_t g_Qh[32ull*2048*96], g_Ql[32ull*2048*96];   // Q packed [bh][s][96p]
__device__ uint32_t g_Kh[32ull*2048*96], g_Kl[32ull*2048*96];   // K packed
__device__ uint32_t g_Vh[32ull*128*1024], g_Vl[32ull*128*1024]; // V^T packed [bh][dv][1024 s-pairs]
__device__ uint32_t g_at_h[4096u*1024], g_at_l[4096u*1024];     // attn out packed [4096][1024p]
__device__ float    g_ropeC[2048*32], g_ropeS[2048*32];

// ================= helpers =================
__device__ __forceinline__ void splitpack(float x0, float x1, uint32_t& h, uint32_t& l) {
    uint32_t hb;
    asm("cvt.rn.bf16x2.f32 %0, %1, %2;" : "=r"(hb) : "f"(x1), "f"(x0));
    const float h0 = __uint_as_float(hb << 16);
    const float h1 = __uint_as_float(hb & 0xffff0000u);
    uint32_t lb;
    asm("cvt.rn.bf16x2.f32 %0, %1, %2;" : "=r"(lb) : "f"(x1 - h1), "f"(x0 - h0));
    h = hb; l = lb;
}

__device__ __forceinline__ void mma16(float* d, const uint32_t* a, const uint32_t* b) {
    asm volatile("mma.sync.aligned.m16n8k16.row.col.f32.bf16.bf16.f32 "
        "{%0,%1,%2,%3}, {%4,%5,%6,%7}, {%8,%9}, {%0,%1,%2,%3};"
        : "+f"(d[0]), "+f"(d[1]), "+f"(d[2]), "+f"(d[3])
        : "r"(a[0]), "r"(a[1]), "r"(a[2]), "r"(a[3]), "r"(b[0]), "r"(b[1]));
}

__device__ __forceinline__ uint32_t smem_u32(const void* p) {
    uint32_t a;
    asm("{ .reg .u64 t; cvta.to.shared.u64 t, %1; cvt.u32.u64 %0, t; }" : "=r"(a) : "l"(p));
    return a;
}
__device__ __forceinline__ void ldsm4(uint32_t* r, uint32_t addr) {
    asm volatile("ldmatrix.sync.aligned.m8n8.x4.shared.b16 {%0,%1,%2,%3}, [%4];"
        : "=r"(r[0]), "=r"(r[1]), "=r"(r[2]), "=r"(r[3]) : "r"(addr));
}
__device__ __forceinline__ void ldsm2(uint32_t* r, uint32_t addr) {
    asm volatile("ldmatrix.sync.aligned.m8n8.x2.shared.b16 {%0,%1}, [%2];"
        : "=r"(r[0]), "=r"(r[1]) : "r"(addr));
}
__device__ __forceinline__ void cpa16(uint32_t dst, const void* src) {
    asm volatile("cp.async.cg.shared.global [%0], [%1], 16;" :: "r"(dst), "l"(src));
}
__device__ __forceinline__ void cpa16z(uint32_t dst, const void* src, int ssz) {
    asm volatile("cp.async.cg.shared.global [%0], [%1], 16, %2;" :: "r"(dst), "l"(src), "r"(ssz));
}
__device__ __forceinline__ void cpa_commit() { asm volatile("cp.async.commit_group;" ::: "memory"); }
template<int NN> __device__ __forceinline__ void cpa_wait() {
    asm volatile("cp.async.wait_group %0;" :: "n"(NN) : "memory");
}

// ================= fused split: all fp32 inputs -> packed bf16 hi/lo =================
#define NP_X    4194304
#define NP_WQD  1572864
#define NP_WKVD  524288
#define NP_WKR    65536
#define NP_WQU  1572864
#define NP_WQR   786432
#define NP_WKVU 1048576
#define NP_WO   2097152
#define NP_TOTAL (NP_X+NP_WQD+NP_WKVD+NP_WKR+NP_WQU+NP_WQR+NP_WKVU+NP_WO)

__global__ __launch_bounds__(256) void split_all(
    const float* __restrict__ x,   const float* __restrict__ wqd,
    const float* __restrict__ wkvd,const float* __restrict__ wkr,
    const float* __restrict__ wqu, const float* __restrict__ wqr,
    const float* __restrict__ wkvu,const float* __restrict__ wo) {
    long long i = (long long)blockIdx.x * 256 + threadIdx.x;
    if (i >= NP_TOTAL) return;
    const float2* s; uint32_t *h, *l;
    long long j = i;
    if (j < NP_X)                    { s = (const float2*)x;    h = g_xs_h;                      l = g_xs_l; }
    else if ((j -= NP_X)   < NP_WQD) { s = (const float2*)wqd;  h = g_wd_h;                      l = g_wd_l; }
    else if ((j -= NP_WQD) < NP_WKVD){ s = (const float2*)wkvd; h = g_wd_h + NP_WQD;             l = g_wd_l + NP_WQD; }
    else if ((j -= NP_WKVD)< NP_WKR) { s = (const float2*)wkr;  h = g_wd_h + NP_WQD + NP_WKVD;   l = g_wd_l + NP_WQD + NP_WKVD; }
    else if ((j -= NP_WKR) < NP_WQU) { s = (const float2*)wqu;  h = g_wqc_h;                     l = g_wqc_l; }
    else if ((j -= NP_WQU) < NP_WQR) { s = (const float2*)wqr;  h = g_wqc_h + NP_WQU;            l = g_wqc_l + NP_WQU; }
    else if ((j -= NP_WQR) < NP_WKVU){ s = (const float2*)wkvu; h = g_wkvu_h;                    l = g_wkvu_l; }
    else    { j -= NP_WKVU;            s = (const float2*)wo;   h = g_wo_h;                      l = g_wo_l; }
    const float2 v = s[j];
    splitpack(v.x, v.y, h[j], l[j]);
}

// ================= packed bf16x3 GEMM: C[M,N] = A[M,K] @ B[N,K]^T =================
#define GP 20
#define GEMM_SMEM (2 * 40960)
__global__ __launch_bounds__(256, 2) void gemm_pk(
    const uint32_t* __restrict__ Ahg, const uint32_t* __restrict__ Alg,
    const uint32_t* __restrict__ Bhg, const uint32_t* __restrict__ Blg,
    float* __restrict__ C, int M, int N, int Kp) {
    extern __shared__ uint32_t gsm[];
    const int tid = threadIdx.x, bx = blockIdx.x, by = blockIdx.y;
    const int w = tid >> 5, lane = tid & 31;
    const int wm = (w >> 2) * 64, wn = (w & 3) * 32;
    const int lrow = tid >> 1, lp = (tid & 1) * 8;
    const int rowA = lane & 15, kselA = (lane >> 4) << 2;
    const int rowB = lane & 7,  kselB = ((lane >> 3) & 1) << 2;
    const uint32_t sbase = smem_u32(gsm);

    const uint32_t* Aph = Ahg + (size_t)(by*128 + lrow) * Kp + lp;
    const uint32_t* Apl = Alg + (size_t)(by*128 + lrow) * Kp + lp;
    const int brow = bx*128 + lrow;
    const bool bok = brow < N;
    const int ssz = bok ? 16 : 0;
    const size_t boff = (size_t)(bok ? brow : 0) * Kp + lp;
    const uint32_t* Bph = Bhg + boff;
    const uint32_t* Bpl = Blg + boff;

    float acc[4][4][4];
    #pragma unroll
    for (int mt = 0; mt < 4; mt++)
        #pragma unroll
        for (int nt = 0; nt < 4; nt++)
            #pragma unroll
            for (int i = 0; i < 4; i++) acc[mt][nt][i] = 0.f;

    const uint32_t dfill = (uint32_t)(lrow*GP + lp) * 4u;

    const int NC = Kp >> 4;
    {
        const uint32_t base = sbase + dfill;
        cpa16 (base,          Aph);      cpa16 (base + 16,          Aph + 4);
        cpa16 (base + 10240,  Apl);      cpa16 (base + 10240 + 16,  Apl + 4);
        cpa16z(base + 20480,  Bph, ssz); cpa16z(base + 20480 + 16,  Bph + 4, ssz);
        cpa16z(base + 30720,  Bpl, ssz); cpa16z(base + 30720 + 16,  Bpl + 4, ssz);
        cpa_commit();
    }

    for (int kc = 0; kc < NC; kc++) {
        const int cur = kc & 1;
        if (kc + 1 < NC) {
            const uint32_t base = sbase + (cur ^ 1) * 40960 + dfill;
            const int ko = (kc + 1) * 16;
            cpa16 (base,          Aph + ko);      cpa16 (base + 16,          Aph + ko + 4);
            cpa16 (base + 10240,  Apl + ko);      cpa16 (base + 10240 + 16,  Apl + ko + 4);
            cpa16z(base + 20480,  Bph + ko, ssz); cpa16z(base + 20480 + 16,  Bph + ko + 4, ssz);
            cpa16z(base + 30720,  Bpl + ko, ssz); cpa16z(base + 30720 + 16,  Bpl + ko + 4, ssz);
            cpa_commit();
            cpa_wait<1>();
        } else {
            cpa_wait<0>();
        }
        __syncthreads();

        const uint32_t cb = sbase + cur * 40960;
        #pragma unroll
        for (int stp = 0; stp < 2; stp++) {
            const int p0 = stp * 8;
            uint32_t fbh[4][2], fbl[4][2];
            #pragma unroll
            for (int nt = 0; nt < 4; nt++) {
                const uint32_t ob = cb + 20480 + (uint32_t)((wn + nt*8 + rowB)*GP + p0 + kselB) * 4u;
                ldsm2(fbh[nt], ob);
                ldsm2(fbl[nt], ob + 10240);
            }
            #pragma unroll
            for (int mt = 0; mt < 4; mt++) {
                const uint32_t oa = cb + (uint32_t)((wm + mt*16 + rowA)*GP + p0 + kselA) * 4u;
                uint32_t fah[4], fal[4];
                ldsm4(fah, oa);
                ldsm4(fal, oa + 10240);
                #pragma unroll
                for (int nt = 0; nt < 4; nt++) mma16(acc[mt][nt], fah, fbh[nt]);
                #pragma unroll
                for (int nt = 0; nt < 4; nt++) mma16(acc[mt][nt], fah, fbl[nt]);
                #pragma unroll
                for (int nt = 0; nt < 4; nt++) mma16(acc[mt][nt], fal, fbh[nt]);
            }
        }
        __syncthreads();
    }

    const int g = lane >> 2, t = lane & 3;
    #pragma unroll
    for (int mt = 0; mt < 4; mt++) {
        const int row = by*128 + wm + mt*16 + g;
        #pragma unroll
        for (int nt = 0; nt < 4; nt++) {
            const int col = bx*128 + wn + nt*8 + 2*t;
            if (col < N) {
                float* cp = C + (size_t)row * N + col;
                *(float2*)cp                   = make_float2(acc[mt][nt][0], acc[mt][nt][1]);
                *(float2*)(cp + 8 * (size_t)N) = make_float2(acc[mt][nt][2], acc[mt][nt][3]);
            }
        }
    }
}

// ================= RMSNorm + split =================
__global__ __launch_bounds__(256) void rmsnorm_split(const float* __restrict__ x, int stride,
                                                     const float* __restrict__ w, int cols,
                                                     uint32_t* __restrict__ oh,
                                                     uint32_t* __restrict__ ol) {
    const int row = blockIdx.x;
    const float* xr = x + (size_t)row * stride;
    const int tid = threadIdx.x;
    float s = 0.f;
    const float4* x4 = (const float4*)xr;
    for (int c = tid; c < (cols >> 2); c += 256) {
        const float4 v = x4[c];
        s = fmaf(v.x, v.x, s); s = fmaf(v.y, v.y, s);
        s = fmaf(v.z, v.z, s); s = fmaf(v.w, v.w, s);
    }
    __shared__ float red[256];
    red[tid] = s; __syncthreads();
    for (int st = 128; st > 0; st >>= 1) {
        if (tid < st) red[tid] += red[tid + st];
        __syncthreads();
    }
    const float inv = rsqrtf(red[0] / (float)cols + 1e-6f);
    const int pairs = cols >> 1;
    const float2* x2 = (const float2*)xr;
    const float2* w2 = (const float2*)w;
    for (int p = tid; p < pairs; p += 256) {
        const float2 xv = x2[p];
        const float2 wv = w2[p];
        splitpack(xv.x * inv * wv.x, xv.y * inv * wv.y,
                  oh[(size_t)row * pairs + p], ol[(size_t)row * pairs + p]);
    }
}

// ================= RoPE table =================
__global__ void rope_table(float* __restrict__ cosT, float* __restrict__ sinT) {
    const int idx = blockIdx.x * 256 + threadIdx.x;
    if (idx >= 2048 * 32) return;
    const int s = idx >> 5, jp = idx & 31;
    const float inv = powf(10000.0f, -(float)(2*jp) * (1.0f/64.0f));
    float sn, cs; sincosf((float)s * inv, &sn, &cs);
    cosT[idx] = cs; sinT[idx] = sn;
}

// ================= assemble Q packed =================
__global__ __launch_bounds__(256) void assemble_q_pk(const float* __restrict__ qup,
        const float* __restrict__ cosT, const float* __restrict__ sinT,
        uint32_t* __restrict__ Qh, uint32_t* __restrict__ Ql) {
    const int idx = blockIdx.x * 256 + threadIdx.x;
    if (idx >= 32*2048*96) return;
    const int p  = idx % 96;
    const int ts = idx / 96;
    const int s  = ts & 2047;
    const int bh = ts >> 11;
    const int b = bh >> 4, h = bh & 15;
    const int m = b*2048 + s;
    float x0, x1;
    if (p < 64) {
        const float* src = qup + (size_t)m*3072 + h*128 + 2*p;
        x0 = src[0]; x1 = src[1];
    } else {
        const int jp = p - 64;
        const float* src = qup + (size_t)m*3072 + 2048 + h*64 + 2*jp;
        const float c = cosT[s*32 + jp], sn = sinT[s*32 + jp];
        const float a = src[0], bb = src[1];
        x0 = a*c - bb*sn;
        x1 = a*sn + bb*c;
    }
    splitpack(x0, x1, Qh[idx], Ql[idx]);
}

// ================= assemble K packed (krope read from dcat at col 2048) =================
__global__ __launch_bounds__(256) void assemble_k_pk(const float* __restrict__ kvup,
        const float* __restrict__ dcat,
        const float* __restrict__ cosT, const float* __restrict__ sinT,
        uint32_t* __restrict__ Kh, uint32_t* __restrict__ Kl) {
    const int idx = blockIdx.x * 256 + threadIdx.x;
    if (idx >= 32*2048*96) return;
    const int p  = idx % 96;
    const int ts = idx / 96;
    const int s  = ts & 2047;
    const int bh = ts >> 11;
    const int b = bh >> 4, h = bh & 15;
    const int m = b*2048 + s;
    float x0, x1;
    if (p < 64) {
        const float* src = kvup + (size_t)m*4096 + h*256 + 2*p;
        x0 = src[0]; x1 = src[1];
    } else {
        const int jp = p - 64;
        const float* src = dcat + (size_t)m*2112 + 2048 + 2*jp;
        const float c = cosT[s*32 + jp], sn = sinT[s*32 + jp];
        const float a = src[0], bb = src[1];
        x0 = a*c - bb*sn;
        x1 = a*sn + bb*c;
    }
    splitpack(x0, x1, Kh[idx], Kl[idx]);
}

// ================= V transpose + split =================
__global__ void split_v(const float* __restrict__ kvup,
                        uint32_t* __restrict__ Vh, uint32_t* __restrict__ Vl) {
    __shared__ float tile[64][33];
    const int bh = blockIdx.z, b = bh >> 4, h = bh & 15;
    const int s0 = blockIdx.x * 64, dv0 = blockIdx.y * 32;
    const int tx = threadIdx.x, ty = threadIdx.y;
    #pragma unroll
    for (int half = 0; half < 2; half++) {
        const int s = s0 + half*32 + ty;
        tile[half*32 + ty][tx] =
            kvup[((size_t)(b*2048 + s))*4096 + h*256 + 128 + dv0 + tx];
    }
    __syncthreads();
    const float x0 = tile[2*tx][ty], x1 = tile[2*tx + 1][ty];
    uint32_t hh, ll; splitpack(x0, x1, hh, ll);
    const size_t o = ((size_t)bh*128 + dv0 + ty)*1024 + (s0 >> 1) + tx;
    Vh[o] = hh; Vl[o] = ll;
}

// ================= flash attention (causal, packed bf16x3, ldmatrix frags) =================
#define FQP 100
#define FVP 36
#define FPP 36
#define FL_BYTES ((4*64*FQP + 2*128*FVP + 2*64*FPP + 2*128) * 4)
__global__ __launch_bounds__(256) void flash_pk(
    const uint32_t* __restrict__ Qhg, const uint32_t* __restrict__ Qlg,
    const uint32_t* __restrict__ Khg, const uint32_t* __restrict__ Klg,
    const uint32_t* __restrict__ Vhg, const uint32_t* __restrict__ Vlg,
    uint32_t* __restrict__ Oh, uint32_t* __restrict__ Ol) {
    extern __shared__ uint32_t sw[];
    uint32_t* Qsh = sw;
    uint32_t* Qsl = Qsh + 64*FQP;
    uint32_t* Ksh = Qsl + 64*FQP;
    uint32_t* Ksl = Ksh + 64*FQP;
    uint32_t* Vsh = Ksl + 64*FQP;
    uint32_t* Vsl = Vsh + 128*FVP;
    uint32_t* Psh = Vsl + 128*FVP;
    uint32_t* Psl = Psh + 64*FPP;
    float* sMax = (float*)(Psl + 64*FPP);
    float* sSum = sMax + 128;

    const int qt = 31 - blockIdx.x;
    const int bh = blockIdx.y;
    const int b = bh >> 4, h = bh & 15;
    const int tid = threadIdx.x;
    const int w = tid >> 5, lane = tid & 31;
    const int qg = w & 3, nhalf = w >> 2;
    const int g = lane >> 2, t = lane & 3;
    const int qrow = qg * 16;

    const int rowA = lane & 15, kselA = (lane >> 4) << 2;
    const int rowB = lane & 7,  kselB = ((lane >> 3) & 1) << 2;
    const uint32_t aQh = smem_u32(Qsh), aQl = smem_u32(Qsl);
    const uint32_t aKh = smem_u32(Ksh), aKl = smem_u32(Ksl);
    const uint32_t aVh = smem_u32(Vsh), aVl = smem_u32(Vsl);
    const uint32_t aPh = smem_u32(Psh), aPl = smem_u32(Psl);

    {
        const size_t base = ((size_t)bh*2048 + qt*64) * 96;
        for (int i = tid; i < 64*24; i += 256) {
            const int r = i / 24, c = i % 24;
            *(uint4*)&Qsh[r*FQP + c*4] = *(const uint4*)(Qhg + base + (size_t)r*96 + c*4);
            *(uint4*)&Qsl[r*FQP + c*4] = *(const uint4*)(Qlg + base + (size_t)r*96 + c*4);
        }
    }

    float m0 = -INFINITY, m1 = -INFINITY, l0 = 0.f, l1 = 0.f;
    float o[8][4];
    #pragma unroll
    for (int nt = 0; nt < 8; nt++)
        #pragma unroll
        for (int e = 0; e < 4; e++) o[nt][e] = 0.f;

    const float scale = 0.07216878364870323f;   // 1/sqrt(192)

    for (int kt = 0; kt <= qt; kt++) {
        __syncthreads();
        {
            const size_t base = ((size_t)bh*2048 + kt*64) * 96;
            for (int i = tid; i < 64*24; i += 256) {
                const int r = i / 24, c = i % 24;
                *(uint4*)&Ksh[r*FQP + c*4] = *(const uint4*)(Khg + base + (size_t)r*96 + c*4);
                *(uint4*)&Ksl[r*FQP + c*4] = *(const uint4*)(Klg + base + (size_t)r*96 + c*4);
            }
            const size_t vb = (size_t)bh*128*1024 + kt*32;
            for (int i = tid; i < 128*8; i += 256) {
                const int r = i / 8, c = i % 8;
                *(uint4*)&Vsh[r*FVP + c*4] = *(const uint4*)(Vhg + vb + (size_t)r*1024 + c*4);
                *(uint4*)&Vsl[r*FVP + c*4] = *(const uint4*)(Vlg + vb + (size_t)r*1024 + c*4);
            }
        }
        __syncthreads();

        float sa[4][4];
        #pragma unroll
        for (int nt = 0; nt < 4; nt++)
            #pragma unroll
            for (int e = 0; e < 4; e++) sa[nt][e] = 0.f;

        #pragma unroll 4
        for (int st = 0; st < 12; st++) {
            const int p0 = st * 8;
            const uint32_t oq = (uint32_t)((qrow + rowA)*FQP + p0 + kselA) * 4u;
            uint32_t fah[4], fal[4];
            ldsm4(fah, aQh + oq);
            ldsm4(fal, aQl + oq);
            uint32_t fbh[4][2], fbl[4][2];
            #pragma unroll
            for (int nt = 0; nt < 4; nt++) {
                const uint32_t ok = (uint32_t)((nhalf*32 + nt*8 + rowB)*FQP + p0 + kselB) * 4u;
                ldsm2(fbh[nt], aKh + ok);
                ldsm2(fbl[nt], aKl + ok);
            }
            #pragma unroll
            for (int nt = 0; nt < 4; nt++) mma16(sa[nt], fah, fbh[nt]);
            #pragma unroll
            for (int nt = 0; nt < 4; nt++) mma16(sa[nt], fah, fbl[nt]);
            #pragma unroll
            for (int nt = 0; nt < 4; nt++) mma16(sa[nt], fal, fbh[nt]);
        }

        const bool diag = (kt == qt);
        float pm0 = -INFINITY, pm1 = -INFINITY;
        #pragma unroll
        for (int nt = 0; nt < 4; nt++) {
            const int colb = nhalf*32 + nt*8 + 2*t;
            #pragma unroll
            for (int e = 0; e < 4; e++) {
                float v = sa[nt][e] * scale;
                if (diag) {
                    const int col = colb + (e & 1);
                    const int row = qrow + g + ((e >> 1) << 3);
                    if (col > row) v = -INFINITY;
                }
                sa[nt][e] = v;
                if (e < 2) pm0 = fmaxf(pm0, v); else pm1 = fmaxf(pm1, v);
            }
        }
        pm0 = fmaxf(pm0, __shfl_xor_sync(0xffffffffu, pm0, 1));
        pm0 = fmaxf(pm0, __shfl_xor_sync(0xffffffffu, pm0, 2));
        pm1 = fmaxf(pm1, __shfl_xor_sync(0xffffffffu, pm1, 1));
        pm1 = fmaxf(pm1, __shfl_xor_sync(0xffffffffu, pm1, 2));
        if (t == 0) {
            sMax[nhalf*64 + qrow + g]     = pm0;
            sMax[nhalf*64 + qrow + g + 8] = pm1;
        }
        __syncthreads();
        const float mn0 = fmaxf(m0, fmaxf(pm0, sMax[(1 - nhalf)*64 + qrow + g]));
        const float mn1 = fmaxf(m1, fmaxf(pm1, sMax[(1 - nhalf)*64 + qrow + g + 8]));
        const float al0 = __expf(m0 - mn0);
        const float al1 = __expf(m1 - mn1);

        float ps0 = 0.f, ps1 = 0.f;
        #pragma unroll
        for (int nt = 0; nt < 4; nt++) {
            const int pidx = nhalf*16 + nt*4 + t;
            const float p0v = __expf(sa[nt][0] - mn0);
            const float p1v = __expf(sa[nt][1] - mn0);
            const float p2v = __expf(sa[nt][2] - mn1);
            const float p3v = __expf(sa[nt][3] - mn1);
            ps0 += p0v + p1v; ps1 += p2v + p3v;
            splitpack(p0v, p1v, Psh[(qrow + g)*FPP + pidx],     Psl[(qrow + g)*FPP + pidx]);
            splitpack(p2v, p3v, Psh[(qrow + g + 8)*FPP + pidx], Psl[(qrow + g + 8)*FPP + pidx]);
        }
        ps0 += __shfl_xor_sync(0xffffffffu, ps0, 1);
        ps0 += __shfl_xor_sync(0xffffffffu, ps0, 2);
        ps1 += __shfl_xor_sync(0xffffffffu, ps1, 1);
        ps1 += __shfl_xor_sync(0xffffffffu, ps1, 2);
        if (t == 0) {
            sSum[nhalf*64 + qrow + g]     = ps0;
            sSum[nhalf*64 + qrow + g + 8] = ps1;
        }
        __syncthreads();
        l0 = l0 * al0 + ps0 + sSum[(1 - nhalf)*64 + qrow + g];
        l1 = l1 * al1 + ps1 + sSum[(1 - nhalf)*64 + qrow + g + 8];
        m0 = mn0; m1 = mn1;

        #pragma unroll
        for (int nt = 0; nt < 8; nt++) {
            o[nt][0] *= al0; o[nt][1] *= al0;
            o[nt][2] *= al1; o[nt][3] *= al1;
        }

        #pragma unroll
        for (int st = 0; st < 4; st++) {
            const int p0 = st * 8;
            const uint32_t op = (uint32_t)((qrow + rowA)*FPP + p0 + kselA) * 4u;
            uint32_t fah[4], fal[4];
            ldsm4(fah, aPh + op);
            ldsm4(fal, aPl + op);
            #pragma unroll
            for (int hv = 0; hv < 2; hv++) {
                uint32_t fbh[4][2], fbl[4][2];
                #pragma unroll
                for (int n4 = 0; n4 < 4; n4++) {
                    const int nt = hv*4 + n4;
                    const uint32_t ov = (uint32_t)((nhalf*64 + nt*8 + rowB)*FVP + p0 + kselB) * 4u;
                    ldsm2(fbh[n4], aVh + ov);
                    ldsm2(fbl[n4], aVl + ov);
                }
                #pragma unroll
                for (int n4 = 0; n4 < 4; n4++) mma16(o[hv*4 + n4], fah, fbh[n4]);
                #pragma unroll
                for (int n4 = 0; n4 < 4; n4++) mma16(o[hv*4 + n4], fah, fbl[n4]);
                #pragma unroll
                for (int n4 = 0; n4 < 4; n4++) mma16(o[hv*4 + n4], fal, fbh[n4]);
            }
        }
    }

    const float il0 = 1.f / l0, il1 = 1.f / l1;
    const int row0 = b*2048 + qt*64 + qrow + g;
    #pragma unroll
    for (int nt = 0; nt < 8; nt++) {
        const int cp = h*64 + nhalf*32 + nt*4 + t;
        splitpack(o[nt][0]*il0, o[nt][1]*il0, Oh[(size_t)row0*1024 + cp],       Ol[(size_t)row0*1024 + cp]);
        splitpack(o[nt][2]*il1, o[nt][3]*il1, Oh[(size_t)(row0 + 8)*1024 + cp], Ol[(size_t)(row0 + 8)*1024 + cp]);
    }
}

// ================= host orchestration =================
static inline int cdiv(int a, int b) { return (a + b - 1) / b; }

extern "C" void kernel_launch(void* const* d_in, const int* in_sizes, int n_in,
                              void* d_out, int out_size) {
    const float* x        = (const float*)d_in[0];
    const float* wq_down  = (const float*)d_in[1];
    const float* q_norm_w = (const float*)d_in[2];
    const float* wq_up    = (const float*)d_in[3];
    const float* wq_rope  = (const float*)d_in[4];
    const float* wkv_down = (const float*)d_in[5];
    const float* kv_norm_w= (const float*)d_in[6];
    const float* wkv_up   = (const float*)d_in[7];
    const float* wk_rope  = (const float*)d_in[8];
    const float* wo       = (const float*)d_in[9];
    float* out = (float*)d_out;

    uint32_t *xs_h,*xs_l,*wd_h,*wd_l,*wqc_h,*wqc_l,*wkvu_h,*wkvu_l,*wo_h,*wo_l;
    uint32_t *qcs_h,*qcs_l,*kvcs_h,*kvcs_l,*Qh,*Ql,*Kh,*Kl,*Vh,*Vl,*at_h,*at_l;
    float *dcat,*qup,*kvup,*ropeC,*ropeS;
    cudaGetSymbolAddress((void**)&xs_h,  g_xs_h);  cudaGetSymbolAddress((void**)&xs_l,  g_xs_l);
    cudaGetSymbolAddress((void**)&wd_h,  g_wd_h);  cudaGetSymbolAddress((void**)&wd_l,  g_wd_l);
    cudaGetSymbolAddress((void**)&wqc_h, g_wqc_h); cudaGetSymbolAddress((void**)&wqc_l, g_wqc_l);
    cudaGetSymbolAddress((void**)&wkvu_h,g_wkvu_h);cudaGetSymbolAddress((void**)&wkvu_l,g_wkvu_l);
    cudaGetSymbolAddress((void**)&wo_h,  g_wo_h);  cudaGetSymbolAddress((void**)&wo_l,  g_wo_l);
    cudaGetSymbolAddress((void**)&dcat,  g_dcat);
    cudaGetSymbolAddress((void**)&qcs_h, g_qcs_h); cudaGetSymbolAddress((void**)&qcs_l, g_qcs_l);
    cudaGetSymbolAddress((void**)&kvcs_h,g_kvcs_h);cudaGetSymbolAddress((void**)&kvcs_l,g_kvcs_l);
    cudaGetSymbolAddress((void**)&qup,   g_qup);   cudaGetSymbolAddress((void**)&kvup,  g_kvup);
    cudaGetSymbolAddress((void**)&Qh,    g_Qh);    cudaGetSymbolAddress((void**)&Ql,    g_Ql);
    cudaGetSymbolAddress((void**)&Kh,    g_Kh);    cudaGetSymbolAddress((void**)&Kl,    g_Kl);
    cudaGetSymbolAddress((void**)&Vh,    g_Vh);    cudaGetSymbolAddress((void**)&Vl,    g_Vl);
    cudaGetSymbolAddress((void**)&at_h,  g_at_h);  cudaGetSymbolAddress((void**)&at_l,  g_at_l);
    cudaGetSymbolAddress((void**)&ropeC, g_ropeC); cudaGetSymbolAddress((void**)&ropeS, g_ropeS);

    cudaFuncSetAttribute(gemm_pk, cudaFuncAttributeMaxDynamicSharedMemorySize, GEMM_SMEM);
    cudaFuncSetAttribute(flash_pk, cudaFuncAttributeMaxDynamicSharedMemorySize, FL_BYTES);

    // ---- one fused split of all fp32 inputs ----
    split_all<<<cdiv((int)NP_TOTAL, 256), 256>>>(x, wq_down, wkv_down, wk_rope,
                                                 wq_up, wq_rope, wkv_up, wo);
    rope_table<<<cdiv(2048*32, 256), 256>>>(ropeC, ropeS);

    // ---- merged down projection: C[4096][2112] = x @ [wq_down|wkv_down|wk_rope]^T ----
    gemm_pk<<<dim3(17, 32), 256, GEMM_SMEM>>>(xs_h, xs_l, wd_h, wd_l, dcat, 4096, 2112, 1024);

    rmsnorm_split<<<4096, 256>>>(dcat,        2112, q_norm_w,  1536, qcs_h,  qcs_l);
    rmsnorm_split<<<4096, 256>>>(dcat + 1536, 2112, kv_norm_w, 512,  kvcs_h, kvcs_l);

    // ---- up projections ----
    gemm_pk<<<dim3(24, 32), 256, GEMM_SMEM>>>(qcs_h,  qcs_l,  wqc_h,  wqc_l,  qup,  4096, 3072, 768);
    gemm_pk<<<dim3(32, 32), 256, GEMM_SMEM>>>(kvcs_h, kvcs_l, wkvu_h, wkvu_l, kvup, 4096, 4096, 256);

    // ---- assemble packed Q/K/V ----
    assemble_q_pk<<<cdiv(32*2048*96, 256), 256>>>(qup, ropeC, ropeS, Qh, Ql);
    assemble_k_pk<<<cdiv(32*2048*96, 256), 256>>>(kvup, dcat, ropeC, ropeS, Kh, Kl);
    split_v<<<dim3(32, 4, 32), dim3(32, 32)>>>(kvup, Vh, Vl);

    // ---- flash attention ----
    flash_pk<<<dim3(32, 32), 256, FL_BYTES>>>(Qh, Ql, Kh, Kl, Vh, Vl, at_h, at_l);

    // ---- output projection ----
    gemm_pk<<<dim3(16, 32), 256, GEMM_SMEM>>>(at_h, at_l, wo_h, wo_l, out, 4096, 2048, 1024);
}

// round 12
// speedup vs baseline: 1.0004x; 1.0004x over previous
#include <cuda_runtime.h>
#include <math.h>
#include <stdint.h>

// ================= static scratch (no allocations allowed) =================
__device__ uint32_t g_xs_h [4096u*1024], g_xs_l [4096u*1024];   // x split [4096][1024p]
__device__ uint32_t g_wd_h [2112u*1024], g_wd_l [2112u*1024];   // wq_down(1536)|wkv_down(512)|wk_rope(64)
__device__ uint32_t g_wqc_h[3072u*768],  g_wqc_l[3072u*768];    // wq_up(2048) | wq_rope(1024)
__device__ uint32_t g_wkvu_h[4096u*256], g_wkvu_l[4096u*256];   // wkv_up
__device__ uint32_t g_wo_h [2048u*1024], g_wo_l [2048u*1024];   // wo
__device__ float    g_dcat [4096u*2112];                        // q_c(1536) | kv_c(512) | krope(64)
__device__ uint32_t g_qcs_h[4096u*768],  g_qcs_l[4096u*768];    // normed q_c split
__device__ uint32_t g_kvcs_h[4096u*256], g_kvcs_l[4096u*256];   // normed kv_c split
__device__ float    g_qup  [4096ull*3072];                      // qnope(2048) | qpe(1024)
__device__ float    g_kvup [4096ull*4096];                      // per head: k_nope(128)|v(128)
__device__ uint32_t g_Qh[32ull*2048*96], g_Ql[32ull*2048*96];   // Q packed [bh][s][96p]
__device__ uint32_t g_Kh[32ull*2048*96], g_Kl[32ull*2048*96];   // K packed
__device__ uint32_t g_Vh[32ull*128*1024], g_Vl[32ull*128*1024]; // V^T packed [bh][dv][1024 s-pairs]
__device__ uint32_t g_at_h[4096u*1024], g_at_l[4096u*1024];     // attn out packed [4096][1024p]
__device__ float    g_ropeC[2048*32], g_ropeS[2048*32];

// ================= helpers =================
__device__ __forceinline__ void splitpack(float x0, float x1, uint32_t& h, uint32_t& l) {
    uint32_t hb;
    asm("cvt.rn.bf16x2.f32 %0, %1, %2;" : "=r"(hb) : "f"(x1), "f"(x0));
    const float h0 = __uint_as_float(hb << 16);
    const float h1 = __uint_as_float(hb & 0xffff0000u);
    uint32_t lb;
    asm("cvt.rn.bf16x2.f32 %0, %1, %2;" : "=r"(lb) : "f"(x1 - h1), "f"(x0 - h0));
    h = hb; l = lb;
}

__device__ __forceinline__ void mma16(float* d, const uint32_t* a, const uint32_t* b) {
    asm volatile("mma.sync.aligned.m16n8k16.row.col.f32.bf16.bf16.f32 "
        "{%0,%1,%2,%3}, {%4,%5,%6,%7}, {%8,%9}, {%0,%1,%2,%3};"
        : "+f"(d[0]), "+f"(d[1]), "+f"(d[2]), "+f"(d[3])
        : "r"(a[0]), "r"(a[1]), "r"(a[2]), "r"(a[3]), "r"(b[0]), "r"(b[1]));
}

__device__ __forceinline__ uint32_t smem_u32(const void* p) {
    uint32_t a;
    asm("{ .reg .u64 t; cvta.to.shared.u64 t, %1; cvt.u32.u64 %0, t; }" : "=r"(a) : "l"(p));
    return a;
}
__device__ __forceinline__ void ldsm4(uint32_t* r, uint32_t addr) {
    asm volatile("ldmatrix.sync.aligned.m8n8.x4.shared.b16 {%0,%1,%2,%3}, [%4];"
        : "=r"(r[0]), "=r"(r[1]), "=r"(r[2]), "=r"(r[3]) : "r"(addr));
}
__device__ __forceinline__ void ldsm2(uint32_t* r, uint32_t addr) {
    asm volatile("ldmatrix.sync.aligned.m8n8.x2.shared.b16 {%0,%1}, [%2];"
        : "=r"(r[0]), "=r"(r[1]) : "r"(addr));
}
__device__ __forceinline__ void cpa16(uint32_t dst, const void* src) {
    asm volatile("cp.async.cg.shared.global [%0], [%1], 16;" :: "r"(dst), "l"(src));
}
__device__ __forceinline__ void cpa16z(uint32_t dst, const void* src, int ssz) {
    asm volatile("cp.async.cg.shared.global [%0], [%1], 16, %2;" :: "r"(dst), "l"(src), "r"(ssz));
}
__device__ __forceinline__ void cpa_commit() { asm volatile("cp.async.commit_group;" ::: "memory"); }
template<int NN> __device__ __forceinline__ void cpa_wait() {
    asm volatile("cp.async.wait_group %0;" :: "n"(NN) : "memory");
}

// ================= fused split: all fp32 inputs -> packed bf16 hi/lo =================
#define NP_X    4194304
#define NP_WQD  1572864
#define NP_WKVD  524288
#define NP_WKR    65536
#define NP_WQU  1572864
#define NP_WQR   786432
#define NP_WKVU 1048576
#define NP_WO   2097152
#define NP_TOTAL (NP_X+NP_WQD+NP_WKVD+NP_WKR+NP_WQU+NP_WQR+NP_WKVU+NP_WO)

__global__ __launch_bounds__(256) void split_all(
    const float* __restrict__ x,   const float* __restrict__ wqd,
    const float* __restrict__ wkvd,const float* __restrict__ wkr,
    const float* __restrict__ wqu, const float* __restrict__ wqr,
    const float* __restrict__ wkvu,const float* __restrict__ wo) {
    long long i = (long long)blockIdx.x * 256 + threadIdx.x;
    if (i >= NP_TOTAL) return;
    const float2* s; uint32_t *h, *l;
    long long j = i;
    if (j < NP_X)                    { s = (const float2*)x;    h = g_xs_h;                      l = g_xs_l; }
    else if ((j -= NP_X)   < NP_WQD) { s = (const float2*)wqd;  h = g_wd_h;                      l = g_wd_l; }
    else if ((j -= NP_WQD) < NP_WKVD){ s = (const float2*)wkvd; h = g_wd_h + NP_WQD;             l = g_wd_l + NP_WQD; }
    else if ((j -= NP_WKVD)< NP_WKR) { s = (const float2*)wkr;  h = g_wd_h + NP_WQD + NP_WKVD;   l = g_wd_l + NP_WQD + NP_WKVD; }
    else if ((j -= NP_WKR) < NP_WQU) { s = (const float2*)wqu;  h = g_wqc_h;                     l = g_wqc_l; }
    else if ((j -= NP_WQU) < NP_WQR) { s = (const float2*)wqr;  h = g_wqc_h + NP_WQU;            l = g_wqc_l + NP_WQU; }
    else if ((j -= NP_WQR) < NP_WKVU){ s = (const float2*)wkvu; h = g_wkvu_h;                    l = g_wkvu_l; }
    else    { j -= NP_WKVU;            s = (const float2*)wo;   h = g_wo_h;                      l = g_wo_l; }
    const float2 v = s[j];
    splitpack(v.x, v.y, h[j], l[j]);
}

// ================= packed bf16x3 GEMM: C[M,N] = A[M,K] @ B[N,K]^T =================
#define GP 20
#define GEMM_SMEM (2 * 40960)
__global__ __launch_bounds__(256, 2) void gemm_pk(
    const uint32_t* __restrict__ Ahg, const uint32_t* __restrict__ Alg,
    const uint32_t* __restrict__ Bhg, const uint32_t* __restrict__ Blg,
    float* __restrict__ C, int M, int N, int Kp) {
    extern __shared__ uint32_t gsm[];
    const int tid = threadIdx.x, bx = blockIdx.x, by = blockIdx.y;
    const int w = tid >> 5, lane = tid & 31;
    const int wm = (w >> 2) * 64, wn = (w & 3) * 32;
    const int lrow = tid >> 1, lp = (tid & 1) * 8;
    const int rowA = lane & 15, kselA = (lane >> 4) << 2;
    const int rowB = lane & 7,  kselB = ((lane >> 3) & 1) << 2;
    const uint32_t sbase = smem_u32(gsm);

    const uint32_t* Aph = Ahg + (size_t)(by*128 + lrow) * Kp + lp;
    const uint32_t* Apl = Alg + (size_t)(by*128 + lrow) * Kp + lp;
    const int brow = bx*128 + lrow;
    const bool bok = brow < N;
    const int ssz = bok ? 16 : 0;
    const size_t boff = (size_t)(bok ? brow : 0) * Kp + lp;
    const uint32_t* Bph = Bhg + boff;
    const uint32_t* Bpl = Blg + boff;

    float acc[4][4][4];
    #pragma unroll
    for (int mt = 0; mt < 4; mt++)
        #pragma unroll
        for (int nt = 0; nt < 4; nt++)
            #pragma unroll
            for (int i = 0; i < 4; i++) acc[mt][nt][i] = 0.f;

    const uint32_t dfill = (uint32_t)(lrow*GP + lp) * 4u;

    const int NC = Kp >> 4;
    {
        const uint32_t base = sbase + dfill;
        cpa16 (base,          Aph);      cpa16 (base + 16,          Aph + 4);
        cpa16 (base + 10240,  Apl);      cpa16 (base + 10240 + 16,  Apl + 4);
        cpa16z(base + 20480,  Bph, ssz); cpa16z(base + 20480 + 16,  Bph + 4, ssz);
        cpa16z(base + 30720,  Bpl, ssz); cpa16z(base + 30720 + 16,  Bpl + 4, ssz);
        cpa_commit();
    }

    for (int kc = 0; kc < NC; kc++) {
        const int cur = kc & 1;
        if (kc + 1 < NC) {
            const uint32_t base = sbase + (cur ^ 1) * 40960 + dfill;
            const int ko = (kc + 1) * 16;
            cpa16 (base,          Aph + ko);      cpa16 (base + 16,          Aph + ko + 4);
            cpa16 (base + 10240,  Apl + ko);      cpa16 (base + 10240 + 16,  Apl + ko + 4);
            cpa16z(base + 20480,  Bph + ko, ssz); cpa16z(base + 20480 + 16,  Bph + ko + 4, ssz);
            cpa16z(base + 30720,  Bpl + ko, ssz); cpa16z(base + 30720 + 16,  Bpl + ko + 4, ssz);
            cpa_commit();
            cpa_wait<1>();
        } else {
            cpa_wait<0>();
        }
        __syncthreads();

        const uint32_t cb = sbase + cur * 40960;
        #pragma unroll
        for (int stp = 0; stp < 2; stp++) {
            const int p0 = stp * 8;
            uint32_t fbh[4][2], fbl[4][2];
            #pragma unroll
            for (int nt = 0; nt < 4; nt++) {
                const uint32_t ob = cb + 20480 + (uint32_t)((wn + nt*8 + rowB)*GP + p0 + kselB) * 4u;
                ldsm2(fbh[nt], ob);
                ldsm2(fbl[nt], ob + 10240);
            }
            #pragma unroll
            for (int mt = 0; mt < 4; mt++) {
                const uint32_t oa = cb + (uint32_t)((wm + mt*16 + rowA)*GP + p0 + kselA) * 4u;
                uint32_t fah[4], fal[4];
                ldsm4(fah, oa);
                ldsm4(fal, oa + 10240);
                #pragma unroll
                for (int nt = 0; nt < 4; nt++) mma16(acc[mt][nt], fah, fbh[nt]);
                #pragma unroll
                for (int nt = 0; nt < 4; nt++) mma16(acc[mt][nt], fah, fbl[nt]);
                #pragma unroll
                for (int nt = 0; nt < 4; nt++) mma16(acc[mt][nt], fal, fbh[nt]);
            }
        }
        __syncthreads();
    }

    const int g = lane >> 2, t = lane & 3;
    #pragma unroll
    for (int mt = 0; mt < 4; mt++) {
        const int row = by*128 + wm + mt*16 + g;
        #pragma unroll
        for (int nt = 0; nt < 4; nt++) {
            const int col = bx*128 + wn + nt*8 + 2*t;
            if (col < N) {
                float* cp = C + (size_t)row * N + col;
                *(float2*)cp                   = make_float2(acc[mt][nt][0], acc[mt][nt][1]);
                *(float2*)(cp + 8 * (size_t)N) = make_float2(acc[mt][nt][2], acc[mt][nt][3]);
            }
        }
    }
}

// ================= RMSNorm + split =================
__global__ __launch_bounds__(256) void rmsnorm_split(const float* __restrict__ x, int stride,
                                                     const float* __restrict__ w, int cols,
                                                     uint32_t* __restrict__ oh,
                                                     uint32_t* __restrict__ ol) {
    const int row = blockIdx.x;
    const float* xr = x + (size_t)row * stride;
    const int tid = threadIdx.x;
    float s = 0.f;
    const float4* x4 = (const float4*)xr;
    for (int c = tid; c < (cols >> 2); c += 256) {
        const float4 v = x4[c];
        s = fmaf(v.x, v.x, s); s = fmaf(v.y, v.y, s);
        s = fmaf(v.z, v.z, s); s = fmaf(v.w, v.w, s);
    }
    __shared__ float red[256];
    red[tid] = s; __syncthreads();
    for (int st = 128; st > 0; st >>= 1) {
        if (tid < st) red[tid] += red[tid + st];
        __syncthreads();
    }
    const float inv = rsqrtf(red[0] / (float)cols + 1e-6f);
    const int pairs = cols >> 1;
    const float2* x2 = (const float2*)xr;
    const float2* w2 = (const float2*)w;
    for (int p = tid; p < pairs; p += 256) {
        const float2 xv = x2[p];
        const float2 wv = w2[p];
        splitpack(xv.x * inv * wv.x, xv.y * inv * wv.y,
                  oh[(size_t)row * pairs + p], ol[(size_t)row * pairs + p]);
    }
}

// ================= RoPE table =================
__global__ void rope_table(float* __restrict__ cosT, float* __restrict__ sinT) {
    const int idx = blockIdx.x * 256 + threadIdx.x;
    if (idx >= 2048 * 32) return;
    const int s = idx >> 5, jp = idx & 31;
    const float inv = powf(10000.0f, -(float)(2*jp) * (1.0f/64.0f));
    float sn, cs; sincosf((float)s * inv, &sn, &cs);
    cosT[idx] = cs; sinT[idx] = sn;
}

// ================= assemble Q packed =================
__global__ __launch_bounds__(256) void assemble_q_pk(const float* __restrict__ qup,
        const float* __restrict__ cosT, const float* __restrict__ sinT,
        uint32_t* __restrict__ Qh, uint32_t* __restrict__ Ql) {
    const int idx = blockIdx.x * 256 + threadIdx.x;
    if (idx >= 32*2048*96) return;
    const int p  = idx % 96;
    const int ts = idx / 96;
    const int s  = ts & 2047;
    const int bh = ts >> 11;
    const int b = bh >> 4, h = bh & 15;
    const int m = b*2048 + s;
    float x0, x1;
    if (p < 64) {
        const float* src = qup + (size_t)m*3072 + h*128 + 2*p;
        x0 = src[0]; x1 = src[1];
    } else {
        const int jp = p - 64;
        const float* src = qup + (size_t)m*3072 + 2048 + h*64 + 2*jp;
        const float c = cosT[s*32 + jp], sn = sinT[s*32 + jp];
        const float a = src[0], bb = src[1];
        x0 = a*c - bb*sn;
        x1 = a*sn + bb*c;
    }
    splitpack(x0, x1, Qh[idx], Ql[idx]);
}

// ================= assemble K packed (krope read from dcat at col 2048) =================
__global__ __launch_bounds__(256) void assemble_k_pk(const float* __restrict__ kvup,
        const float* __restrict__ dcat,
        const float* __restrict__ cosT, const float* __restrict__ sinT,
        uint32_t* __restrict__ Kh, uint32_t* __restrict__ Kl) {
    const int idx = blockIdx.x * 256 + threadIdx.x;
    if (idx >= 32*2048*96) return;
    const int p  = idx % 96;
    const int ts = idx / 96;
    const int s  = ts & 2047;
    const int bh = ts >> 11;
    const int b = bh >> 4, h = bh & 15;
    const int m = b*2048 + s;
    float x0, x1;
    if (p < 64) {
        const float* src = kvup + (size_t)m*4096 + h*256 + 2*p;
        x0 = src[0]; x1 = src[1];
    } else {
        const int jp = p - 64;
        const float* src = dcat + (size_t)m*2112 + 2048 + 2*jp;
        const float c = cosT[s*32 + jp], sn = sinT[s*32 + jp];
        const float a = src[0], bb = src[1];
        x0 = a*c - bb*sn;
        x1 = a*sn + bb*c;
    }
    splitpack(x0, x1, Kh[idx], Kl[idx]);
}

// ================= V transpose + split =================
__global__ void split_v(const float* __restrict__ kvup,
                        uint32_t* __restrict__ Vh, uint32_t* __restrict__ Vl) {
    __shared__ float tile[64][33];
    const int bh = blockIdx.z, b = bh >> 4, h = bh & 15;
    const int s0 = blockIdx.x * 64, dv0 = blockIdx.y * 32;
    const int tx = threadIdx.x, ty = threadIdx.y;
    #pragma unroll
    for (int half = 0; half < 2; half++) {
        const int s = s0 + half*32 + ty;
        tile[half*32 + ty][tx] =
            kvup[((size_t)(b*2048 + s))*4096 + h*256 + 128 + dv0 + tx];
    }
    __syncthreads();
    const float x0 = tile[2*tx][ty], x1 = tile[2*tx + 1][ty];
    uint32_t hh, ll; splitpack(x0, x1, hh, ll);
    const size_t o = ((size_t)bh*128 + dv0 + ty)*1024 + (s0 >> 1) + tx;
    Vh[o] = hh; Vl[o] = ll;
}

// ================= flash attention (causal, packed bf16x3, ldmatrix frags) =================
#define FQP 100
#define FVP 36
#define FPP 36
#define FL_BYTES ((4*64*FQP + 2*128*FVP + 2*64*FPP + 2*128) * 4)
__global__ __launch_bounds__(256) void flash_pk(
    const uint32_t* __restrict__ Qhg, const uint32_t* __restrict__ Qlg,
    const uint32_t* __restrict__ Khg, const uint32_t* __restrict__ Klg,
    const uint32_t* __restrict__ Vhg, const uint32_t* __restrict__ Vlg,
    uint32_t* __restrict__ Oh, uint32_t* __restrict__ Ol) {
    extern __shared__ uint32_t sw[];
    uint32_t* Qsh = sw;
    uint32_t* Qsl = Qsh + 64*FQP;
    uint32_t* Ksh = Qsl + 64*FQP;
    uint32_t* Ksl = Ksh + 64*FQP;
    uint32_t* Vsh = Ksl + 64*FQP;
    uint32_t* Vsl = Vsh + 128*FVP;
    uint32_t* Psh = Vsl + 128*FVP;
    uint32_t* Psl = Psh + 64*FPP;
    float* sMax = (float*)(Psl + 64*FPP);
    float* sSum = sMax + 128;

    const int qt = 31 - blockIdx.x;
    const int bh = blockIdx.y;
    const int b = bh >> 4, h = bh & 15;
    const int tid = threadIdx.x;
    const int w = tid >> 5, lane = tid & 31;
    const int qg = w & 3, nhalf = w >> 2;
    const int g = lane >> 2, t = lane & 3;
    const int qrow = qg * 16;

    const int rowA = lane & 15, kselA = (lane >> 4) << 2;
    const int rowB = lane & 7,  kselB = ((lane >> 3) & 1) << 2;
    const uint32_t aQh = smem_u32(Qsh), aQl = smem_u32(Qsl);
    const uint32_t aKh = smem_u32(Ksh), aKl = smem_u32(Ksl);
    const uint32_t aVh = smem_u32(Vsh), aVl = smem_u32(Vsl);
    const uint32_t aPh = smem_u32(Psh), aPl = smem_u32(Psl);

    {
        const size_t base = ((size_t)bh*2048 + qt*64) * 96;
        for (int i = tid; i < 64*24; i += 256) {
            const int r = i / 24, c = i % 24;
            *(uint4*)&Qsh[r*FQP + c*4] = *(const uint4*)(Qhg + base + (size_t)r*96 + c*4);
            *(uint4*)&Qsl[r*FQP + c*4] = *(const uint4*)(Qlg + base + (size_t)r*96 + c*4);
        }
    }

    float m0 = -INFINITY, m1 = -INFINITY, l0 = 0.f, l1 = 0.f;
    float o[8][4];
    #pragma unroll
    for (int nt = 0; nt < 8; nt++)
        #pragma unroll
        for (int e = 0; e < 4; e++) o[nt][e] = 0.f;

    const float scale = 0.07216878364870323f;   // 1/sqrt(192)

    for (int kt = 0; kt <= qt; kt++) {
        __syncthreads();
        {
            const size_t base = ((size_t)bh*2048 + kt*64) * 96;
            for (int i = tid; i < 64*24; i += 256) {
                const int r = i / 24, c = i % 24;
                *(uint4*)&Ksh[r*FQP + c*4] = *(const uint4*)(Khg + base + (size_t)r*96 + c*4);
                *(uint4*)&Ksl[r*FQP + c*4] = *(const uint4*)(Klg + base + (size_t)r*96 + c*4);
            }
            const size_t vb = (size_t)bh*128*1024 + kt*32;
            for (int i = tid; i < 128*8; i += 256) {
                const int r = i / 8, c = i % 8;
                *(uint4*)&Vsh[r*FVP + c*4] = *(const uint4*)(Vhg + vb + (size_t)r*1024 + c*4);
                *(uint4*)&Vsl[r*FVP + c*4] = *(const uint4*)(Vlg + vb + (size_t)r*1024 + c*4);
            }
        }
        __syncthreads();

        float sa[4][4];
        #pragma unroll
        for (int nt = 0; nt < 4; nt++)
            #pragma unroll
            for (int e = 0; e < 4; e++) sa[nt][e] = 0.f;

        #pragma unroll 4
        for (int st = 0; st < 12; st++) {
            const int p0 = st * 8;
            const uint32_t oq = (uint32_t)((qrow + rowA)*FQP + p0 + kselA) * 4u;
            uint32_t fah[4], fal[4];
            ldsm4(fah, aQh + oq);
            ldsm4(fal, aQl + oq);
            uint32_t fbh[4][2], fbl[4][2];
            #pragma unroll
            for (int nt = 0; nt < 4; nt++) {
                const uint32_t ok = (uint32_t)((nhalf*32 + nt*8 + rowB)*FQP + p0 + kselB) * 4u;
                ldsm2(fbh[nt], aKh + ok);
                ldsm2(fbl[nt], aKl + ok);
            }
            #pragma unroll
            for (int nt = 0; nt < 4; nt++) mma16(sa[nt], fah, fbh[nt]);
            #pragma unroll
            for (int nt = 0; nt < 4; nt++) mma16(sa[nt], fah, fbl[nt]);
            #pragma unroll
            for (int nt = 0; nt < 4; nt++) mma16(sa[nt], fal, fbh[nt]);
        }

        const bool diag = (kt == qt);
        float pm0 = -INFINITY, pm1 = -INFINITY;
        #pragma unroll
        for (int nt = 0; nt < 4; nt++) {
            const int colb = nhalf*32 + nt*8 + 2*t;
            #pragma unroll
            for (int e = 0; e < 4; e++) {
                float v = sa[nt][e] * scale;
                if (diag) {
                    const int col = colb + (e & 1);
                    const int row = qrow + g + ((e >> 1) << 3);
                    if (col > row) v = -INFINITY;
                }
                sa[nt][e] = v;
                if (e < 2) pm0 = fmaxf(pm0, v); else pm1 = fmaxf(pm1, v);
            }
        }
        pm0 = fmaxf(pm0, __shfl_xor_sync(0xffffffffu, pm0, 1));
        pm0 = fmaxf(pm0, __shfl_xor_sync(0xffffffffu, pm0, 2));
        pm1 = fmaxf(pm1, __shfl_xor_sync(0xffffffffu, pm1, 1));
        pm1 = fmaxf(pm1, __shfl_xor_sync(0xffffffffu, pm1, 2));
        if (t == 0) {
            sMax[nhalf*64 + qrow + g]     = pm0;
            sMax[nhalf*64 + qrow + g + 8] = pm1;
        }
        __syncthreads();
        const float mn0 = fmaxf(m0, fmaxf(pm0, sMax[(1 - nhalf)*64 + qrow + g]));
        const float mn1 = fmaxf(m1, fmaxf(pm1, sMax[(1 - nhalf)*64 + qrow + g + 8]));
        const float al0 = __expf(m0 - mn0);
        const float al1 = __expf(m1 - mn1);

        float ps0 = 0.f, ps1 = 0.f;
        #pragma unroll
        for (int nt = 0; nt < 4; nt++) {
            const int pidx = nhalf*16 + nt*4 + t;
            const float p0v = __expf(sa[nt][0] - mn0);
            const float p1v = __expf(sa[nt][1] - mn0);
            const float p2v = __expf(sa[nt][2] - mn1);
            const float p3v = __expf(sa[nt][3] - mn1);
            ps0 += p0v + p1v; ps1 += p2v + p3v;
            splitpack(p0v, p1v, Psh[(qrow + g)*FPP + pidx],     Psl[(qrow + g)*FPP + pidx]);
            splitpack(p2v, p3v, Psh[(qrow + g + 8)*FPP + pidx], Psl[(qrow + g + 8)*FPP + pidx]);
        }
        ps0 += __shfl_xor_sync(0xffffffffu, ps0, 1);
        ps0 += __shfl_xor_sync(0xffffffffu, ps0, 2);
        ps1 += __shfl_xor_sync(0xffffffffu, ps1, 1);
        ps1 += __shfl_xor_sync(0xffffffffu, ps1, 2);
        if (t == 0) {
            sSum[nhalf*64 + qrow + g]     = ps0;
            sSum[nhalf*64 + qrow + g + 8] = ps1;
        }
        __syncthreads();
        l0 = l0 * al0 + ps0 + sSum[(1 - nhalf)*64 + qrow + g];
        l1 = l1 * al1 + ps1 + sSum[(1 - nhalf)*64 + qrow + g + 8];
        m0 = mn0; m1 = mn1;

        #pragma unroll
        for (int nt = 0; nt < 8; nt++) {
            o[nt][0] *= al0; o[nt][1] *= al0;
            o[nt][2] *= al1; o[nt][3] *= al1;
        }

        #pragma unroll
        for (int st = 0; st < 4; st++) {
            const int p0 = st * 8;
            const uint32_t op = (uint32_t)((qrow + rowA)*FPP + p0 + kselA) * 4u;
            uint32_t fah[4], fal[4];
            ldsm4(fah, aPh + op);
            ldsm4(fal, aPl + op);
            #pragma unroll
            for (int hv = 0; hv < 2; hv++) {
                uint32_t fbh[4][2], fbl[4][2];
                #pragma unroll
                for (int n4 = 0; n4 < 4; n4++) {
                    const int nt = hv*4 + n4;
                    const uint32_t ov = (uint32_t)((nhalf*64 + nt*8 + rowB)*FVP + p0 + kselB) * 4u;
                    ldsm2(fbh[n4], aVh + ov);
                    ldsm2(fbl[n4], aVl + ov);
                }
                #pragma unroll
                for (int n4 = 0; n4 < 4; n4++) mma16(o[hv*4 + n4], fah, fbh[n4]);
                #pragma unroll
                for (int n4 = 0; n4 < 4; n4++) mma16(o[hv*4 + n4], fah, fbl[n4]);
                #pragma unroll
                for (int n4 = 0; n4 < 4; n4++) mma16(o[hv*4 + n4], fal, fbh[n4]);
            }
        }
    }

    const float il0 = 1.f / l0, il1 = 1.f / l1;
    const int row0 = b*2048 + qt*64 + qrow + g;
    #pragma unroll
    for (int nt = 0; nt < 8; nt++) {
        const int cp = h*64 + nhalf*32 + nt*4 + t;
        splitpack(o[nt][0]*il0, o[nt][1]*il0, Oh[(size_t)row0*1024 + cp],       Ol[(size_t)row0*1024 + cp]);
        splitpack(o[nt][2]*il1, o[nt][3]*il1, Oh[(size_t)(row0 + 8)*1024 + cp], Ol[(size_t)(row0 + 8)*1024 + cp]);
    }
}

// ================= host orchestration =================
static inline int cdiv(int a, int b) { return (a + b - 1) / b; }

extern "C" void kernel_launch(void* const* d_in, const int* in_sizes, int n_in,
                              void* d_out, int out_size) {
    const float* x        = (const float*)d_in[0];
    const float* wq_down  = (const float*)d_in[1];
    const float* q_norm_w = (const float*)d_in[2];
    const float* wq_up    = (const float*)d_in[3];
    const float* wq_rope  = (const float*)d_in[4];
    const float* wkv_down = (const float*)d_in[5];
    const float* kv_norm_w= (const float*)d_in[6];
    const float* wkv_up   = (const float*)d_in[7];
    const float* wk_rope  = (const float*)d_in[8];
    const float* wo       = (const float*)d_in[9];
    float* out = (float*)d_out;

    uint32_t *xs_h,*xs_l,*wd_h,*wd_l,*wqc_h,*wqc_l,*wkvu_h,*wkvu_l,*wo_h,*wo_l;
    uint32_t *qcs_h,*qcs_l,*kvcs_h,*kvcs_l,*Qh,*Ql,*Kh,*Kl,*Vh,*Vl,*at_h,*at_l;
    float *dcat,*qup,*kvup,*ropeC,*ropeS;
    cudaGetSymbolAddress((void**)&xs_h,  g_xs_h);  cudaGetSymbolAddress((void**)&xs_l,  g_xs_l);
    cudaGetSymbolAddress((void**)&wd_h,  g_wd_h);  cudaGetSymbolAddress((void**)&wd_l,  g_wd_l);
    cudaGetSymbolAddress((void**)&wqc_h, g_wqc_h); cudaGetSymbolAddress((void**)&wqc_l, g_wqc_l);
    cudaGetSymbolAddress((void**)&wkvu_h,g_wkvu_h);cudaGetSymbolAddress((void**)&wkvu_l,g_wkvu_l);
    cudaGetSymbolAddress((void**)&wo_h,  g_wo_h);  cudaGetSymbolAddress((void**)&wo_l,  g_wo_l);
    cudaGetSymbolAddress((void**)&dcat,  g_dcat);
    cudaGetSymbolAddress((void**)&qcs_h, g_qcs_h); cudaGetSymbolAddress((void**)&qcs_l, g_qcs_l);
    cudaGetSymbolAddress((void**)&kvcs_h,g_kvcs_h);cudaGetSymbolAddress((void**)&kvcs_l,g_kvcs_l);
    cudaGetSymbolAddress((void**)&qup,   g_qup);   cudaGetSymbolAddress((void**)&kvup,  g_kvup);
    cudaGetSymbolAddress((void**)&Qh,    g_Qh);    cudaGetSymbolAddress((void**)&Ql,    g_Ql);
    cudaGetSymbolAddress((void**)&Kh,    g_Kh);    cudaGetSymbolAddress((void**)&Kl,    g_Kl);
    cudaGetSymbolAddress((void**)&Vh,    g_Vh);    cudaGetSymbolAddress((void**)&Vl,    g_Vl);
    cudaGetSymbolAddress((void**)&at_h,  g_at_h);  cudaGetSymbolAddress((void**)&at_l,  g_at_l);
    cudaGetSymbolAddress((void**)&ropeC, g_ropeC); cudaGetSymbolAddress((void**)&ropeS, g_ropeS);

    cudaFuncSetAttribute(gemm_pk, cudaFuncAttributeMaxDynamicSharedMemorySize, GEMM_SMEM);
    cudaFuncSetAttribute(flash_pk, cudaFuncAttributeMaxDynamicSharedMemorySize, FL_BYTES);

    // ---- one fused split of all fp32 inputs ----
    split_all<<<cdiv((int)NP_TOTAL, 256), 256>>>(x, wq_down, wkv_down, wk_rope,
                                                 wq_up, wq_rope, wkv_up, wo);
    rope_table<<<cdiv(2048*32, 256), 256>>>(ropeC, ropeS);

    // ---- merged down projection: C[4096][2112] = x @ [wq_down|wkv_down|wk_rope]^T ----
    gemm_pk<<<dim3(17, 32), 256, GEMM_SMEM>>>(xs_h, xs_l, wd_h, wd_l, dcat, 4096, 2112, 1024);

    rmsnorm_split<<<4096, 256>>>(dcat,        2112, q_norm_w,  1536, qcs_h,  qcs_l);
    rmsnorm_split<<<4096, 256>>>(dcat + 1536, 2112, kv_norm_w, 512,  kvcs_h, kvcs_l);

    // ---- up projections ----
    gemm_pk<<<dim3(24, 32), 256, GEMM_SMEM>>>(qcs_h,  qcs_l,  wqc_h,  wqc_l,  qup,  4096, 3072, 768);
    gemm_pk<<<dim3(32, 32), 256, GEMM_SMEM>>>(kvcs_h, kvcs_l, wkvu_h, wkvu_l, kvup, 4096, 4096, 256);

    // ---- assemble packed Q/K/V ----
    assemble_q_pk<<<cdiv(32*2048*96, 256), 256>>>(qup, ropeC, ropeS, Qh, Ql);
    assemble_k_pk<<<cdiv(32*2048*96, 256), 256>>>(kvup, dcat, ropeC, ropeS, Kh, Kl);
    split_v<<<dim3(32, 4, 32), dim3(32, 32)>>>(kvup, Vh, Vl);

    // ---- flash attention ----
    flash_pk<<<dim3(32, 32), 256, FL_BYTES>>>(Qh, Ql, Kh, Kl, Vh, Vl, at_h, at_l);

    // ---- output projection ----
    gemm_pk<<<dim3(16, 32), 256, GEMM_SMEM>>>(at_h, at_l, wo_h, wo_l, out, 4096, 2048, 1024);
}